// round 15
// baseline (speedup 1.0000x reference)
#include <cuda_runtime.h>
#include <cuda_bf16.h>
#include <math.h>
#include <cstdint>

// Fixed shapes for HyperbolicMLR_33045478375870
#define BDIM 4096
#define DDIM 1024
#define CDIM 4096
#define EPSV 1e-15f
#define MAXN 0.99999f   // (1 - 1e-5)/sqrt(c), c = 1

// ---------------------------------------------------------------------------
// Device scratch (no allocations allowed)
// ---------------------------------------------------------------------------
__device__ __nv_bfloat16 g_xhi[(size_t)BDIM * DDIM];
__device__ __nv_bfloat16 g_phi[(size_t)CDIM * DDIM];
__device__ __nv_bfloat16 g_ahi[(size_t)CDIM * DDIM];
__device__ float g_x2[BDIM];
__device__ float g_p2[CDIM];
__device__ float g_pa[CDIM];
__device__ float g_an[CDIM];

// ---------------------------------------------------------------------------
__device__ __forceinline__ uint32_t smem_u32(const void* p) {
    uint32_t a;
    asm("{ .reg .u64 t; cvta.to.shared.u64 t, %1; cvt.u32.u64 %0, t; }"
        : "=r"(a) : "l"(p));
    return a;
}

#define LDSM4(r, addr) \
    asm volatile("ldmatrix.sync.aligned.m8n8.x4.shared.b16 {%0,%1,%2,%3}, [%4];" \
                 : "=r"((r)[0]), "=r"((r)[1]), "=r"((r)[2]), "=r"((r)[3]) \
                 : "r"(addr))

#define MMA16816(c, a, b0, b1) \
    asm volatile("mma.sync.aligned.m16n8k16.row.col.f32.bf16.bf16.f32 " \
                 "{%0,%1,%2,%3},{%4,%5,%6,%7},{%8,%9},{%0,%1,%2,%3};" \
                 : "+f"((c)[0]), "+f"((c)[1]), "+f"((c)[2]), "+f"((c)[3]) \
                 : "r"((a)[0]), "r"((a)[1]), "r"((a)[2]), "r"((a)[3]), \
                   "r"(b0), "r"(b1))

#define CP_ASYNC16(dst, src) \
    asm volatile("cp.async.cg.shared.global [%0], [%1], 16;" \
                 :: "r"(dst), "l"(__cvta_generic_to_global(src)))

// Streaming store: write-once output should not evict L2-resident operands.
#define STG_CS_V2(addr, vx, vy) \
    asm volatile("st.global.cs.v2.f32 [%0], {%1, %2};" \
                 :: "l"(addr), "f"(vx), "f"(vy) : "memory")

#define MBARRIER_INIT(mbar, count) \
    asm volatile("mbarrier.init.shared.b64 [%0], %1;" \
                 :: "r"((uint32_t)(mbar)), "r"((uint32_t)(count)) : "memory")

#define MB_ARRIVE(mbar) \
    asm volatile("mbarrier.arrive.shared.b64 _, [%0];" \
                 :: "r"((uint32_t)(mbar)) : "memory")

#define CPX_ARRIVE(mbar) \
    asm volatile("cp.async.mbarrier.arrive.noinc.shared.b64 [%0];" \
                 :: "r"((uint32_t)(mbar)) : "memory")

#define MBARRIER_WAIT_PARITY(mbar, parity) do {                                   \
    uint32_t _mbar = (uint32_t)(mbar);                                            \
    uint32_t _par  = (uint32_t)(parity);                                          \
    uint32_t _done;                                                               \
    asm volatile(                                                                 \
        "{\n\t.reg .pred p;\n\t"                                                  \
        "mbarrier.try_wait.parity.acquire.cta.shared::cta.b64 p, [%1], %2;\n\t"   \
        "selp.b32 %0, 1, 0, p;\n\t}"                                              \
        : "=r"(_done) : "r"(_mbar), "r"(_par) : "memory");                        \
    if (!_done) {                                                                 \
        asm volatile(                                                             \
            "{\n\t.reg .pred P1;\n\t"                                             \
            "WAIT_LOOP_%=:\n\t"                                                   \
            "mbarrier.try_wait.parity.acquire.cta.shared::cta.b64 P1, [%0], %1, 0x989680;\n\t" \
            "@P1 bra.uni WAIT_DONE_%=;\n\t"                                       \
            "bra.uni WAIT_LOOP_%=;\n\t"                                           \
            "WAIT_DONE_%=:\n\t}"                                                  \
            :: "r"(_mbar), "r"(_par) : "memory");                                 \
    }                                                                             \
} while (0)

// Producer wait: post-wait accesses are async-proxy (cp.async) only -> relaxed.
#define MBARRIER_WAIT_PARITY_RELAXED(mbar, parity) do {                           \
    uint32_t _mbar = (uint32_t)(mbar);                                            \
    uint32_t _par  = (uint32_t)(parity);                                          \
    uint32_t _done;                                                               \
    asm volatile(                                                                 \
        "{\n\t.reg .pred p;\n\t"                                                  \
        "mbarrier.try_wait.parity.relaxed.cta.shared::cta.b64 p, [%1], %2;\n\t"   \
        "selp.b32 %0, 1, 0, p;\n\t}"                                              \
        : "=r"(_done) : "r"(_mbar), "r"(_par) : "memory");                        \
    if (!_done) {                                                                 \
        asm volatile(                                                             \
            "{\n\t.reg .pred P1;\n\t"                                             \
            "WAIT_LOOP_%=:\n\t"                                                   \
            "mbarrier.try_wait.parity.relaxed.cta.shared::cta.b64 P1, [%0], %1, 0x989680;\n\t" \
            "@P1 bra.uni WAIT_DONE_%=;\n\t"                                       \
            "bra.uni WAIT_LOOP_%=;\n\t"                                           \
            "WAIT_DONE_%=:\n\t}"                                                  \
            :: "r"(_mbar), "r"(_par) : "memory");                                 \
    }                                                                             \
} while (0)

// ---------------------------------------------------------------------------
// Merged prep kernel (unchanged)
// ---------------------------------------------------------------------------
__global__ __launch_bounds__(256) void prep_kernel(const float* __restrict__ x,
                                                   const float* __restrict__ a,
                                                   const float* __restrict__ p) {
    const int blk = blockIdx.x;
    const int tid = threadIdx.x;
    __shared__ float red[3][8];

    if (blk < BDIM) {
        const int b = blk;
        const float4 v = ((const float4*)(x + (size_t)b * DDIM))[tid];
        float s = v.x * v.x + v.y * v.y + v.z * v.z + v.w * v.w;
        #pragma unroll
        for (int o = 16; o > 0; o >>= 1) s += __shfl_xor_sync(0xFFFFFFFFu, s, o);
        if ((tid & 31) == 0) red[0][tid >> 5] = s;
        __syncthreads();
        __shared__ float sh_scale;
        if (tid == 0) {
            float tot = 0.f;
            #pragma unroll
            for (int w = 0; w < 8; w++) tot += red[0][w];
            float xn = fmaxf(sqrtf(tot), EPSV);
            float scale = (xn > MAXN) ? (MAXN / xn) : 1.0f;
            sh_scale = scale;
            g_x2[b] = tot * scale * scale;
        }
        __syncthreads();
        const float sc = sh_scale;
        __nv_bfloat162 o0 = {__float2bfloat16(v.x * sc), __float2bfloat16(v.y * sc)};
        __nv_bfloat162 o1 = {__float2bfloat16(v.z * sc), __float2bfloat16(v.w * sc)};
        ((__nv_bfloat162*)(g_xhi + (size_t)b * DDIM))[tid * 2]     = o0;
        ((__nv_bfloat162*)(g_xhi + (size_t)b * DDIM))[tid * 2 + 1] = o1;
    } else {
        const int c = blk - BDIM;
        const float4 pv = ((const float4*)(p + (size_t)c * DDIM))[tid];
        const float4 av = ((const float4*)(a + (size_t)c * DDIM))[tid];
        float sp2 = pv.x * pv.x + pv.y * pv.y + pv.z * pv.z + pv.w * pv.w;
        float spa = pv.x * av.x + pv.y * av.y + pv.z * av.z + pv.w * av.w;
        float sa2 = av.x * av.x + av.y * av.y + av.z * av.z + av.w * av.w;
        __nv_bfloat162 p0 = {__float2bfloat16(pv.x), __float2bfloat16(pv.y)};
        __nv_bfloat162 p1 = {__float2bfloat16(pv.z), __float2bfloat16(pv.w)};
        __nv_bfloat162 a0 = {__float2bfloat16(av.x), __float2bfloat16(av.y)};
        __nv_bfloat162 a1 = {__float2bfloat16(av.z), __float2bfloat16(av.w)};
        ((__nv_bfloat162*)(g_phi + (size_t)c * DDIM))[tid * 2]     = p0;
        ((__nv_bfloat162*)(g_phi + (size_t)c * DDIM))[tid * 2 + 1] = p1;
        ((__nv_bfloat162*)(g_ahi + (size_t)c * DDIM))[tid * 2]     = a0;
        ((__nv_bfloat162*)(g_ahi + (size_t)c * DDIM))[tid * 2 + 1] = a1;
        #pragma unroll
        for (int o = 16; o > 0; o >>= 1) {
            sp2 += __shfl_xor_sync(0xFFFFFFFFu, sp2, o);
            spa += __shfl_xor_sync(0xFFFFFFFFu, spa, o);
            sa2 += __shfl_xor_sync(0xFFFFFFFFu, sa2, o);
        }
        if ((tid & 31) == 0) {
            red[0][tid >> 5] = sp2; red[1][tid >> 5] = spa; red[2][tid >> 5] = sa2;
        }
        __syncthreads();
        if (tid == 0) {
            float t0 = 0.f, t1 = 0.f, t2 = 0.f;
            #pragma unroll
            for (int w = 0; w < 8; w++) { t0 += red[0][w]; t1 += red[1][w]; t2 += red[2][w]; }
            g_p2[c] = t0; g_pa[c] = t1; g_an[c] = sqrtf(t2);
        }
    }
}

// ---------------------------------------------------------------------------
// Epilogue math: 1 MUFU (rsqrt), no division, no log. 10-term atanh poly.
// ---------------------------------------------------------------------------
__device__ __forceinline__ float hyp_logit(float px, float xa, float x2,
                                           float p2, float pa, float an) {
    const float A   = 1.0f - 2.0f * px + x2;
    const float Bc  = 1.0f - p2;
    const float den = fmaxf(fmaf(x2, p2, fmaf(-2.0f, px, 1.0f)), EPSV);
    const float w   = fmaxf(fmaf(A * A, p2, fmaf(Bc * Bc, x2, -2.0f * A * Bc * px)), 0.0f);
    const float u   = fmaf(Bc, xa, -A * pa);
    const float N   = 2.0f * u * den;
    const float D   = fmaf(den, den, w) * an;
    const float z   = N * rsqrtf(fmaf(N, N, D * D));
    const float t   = z * z;
    float s = 1.0f / 19.0f;
    s = fmaf(s, t, 1.0f / 17.0f);
    s = fmaf(s, t, 1.0f / 15.0f); s = fmaf(s, t, 1.0f / 13.0f);
    s = fmaf(s, t, 1.0f / 11.0f); s = fmaf(s, t, 1.0f / 9.0f);
    s = fmaf(s, t, 1.0f / 7.0f);  s = fmaf(s, t, 1.0f / 5.0f);
    s = fmaf(s, t, 1.0f / 3.0f);  s = fmaf(s, t, 1.0f);
    return -z * s;
}

// ---------------------------------------------------------------------------
// Main kernel: dual pure-bf16 GEMM via mma.sync + fused epilogue
//   R14 structure (197.0us). ONLY change: free[] mbarriers now count 8 with
//   one elected arrive per warp (LDSM is warp-collective, so lane 0 passing
//   its last LDSM implies the warp is done) -- removes ~248 serialized
//   same-address smem atomics per stage release.
// ---------------------------------------------------------------------------
#define BM 128
#define BN 64
#define BK 64
#define NKIT (DDIM / BK)          // 16
#define ROWB 144                  // 128 data + 16 pad (conflict-free ldmatrix)
#define STAGEB (256 * ROWB)       // 36864
#define STG0 128
#define SMEM_NEED (STG0 + 3 * STAGEB)  // 110720

__global__ __launch_bounds__(256, 2) void mlr_mma_kernel(float* __restrict__ out) {
    extern __shared__ char sm[];
    const uint32_t sb = smem_u32(sm);
    const int tid  = threadIdx.x;
    const int wid  = tid >> 5;
    const int lane = tid & 31;
    const int wn = wid & 3;
    const int wm = wid >> 2;
    const int cb = blockIdx.x * BN;
    const int rb = blockIdx.y * BM;
    const int rot = (wn + (wm << 1)) & 3;   // 4-phase SM-wide spread

    // barriers: full[s] at sb + s*8 (count 256, cp.async tracked);
    //           free[s] at sb + 24 + s*8 (count 8: one arrive per warp)
    if (tid == 0) {
        #pragma unroll
        for (int s = 0; s < 3; s++) {
            MBARRIER_INIT(sb + s * 8, 256);
            MBARRIER_INIT(sb + 24 + s * 8, 8);
        }
    }
    __syncthreads();

    // loader mapping
    const int lr = tid >> 3;
    const int lch = tid & 7;
    const __nv_bfloat16* xb = g_xhi + (size_t)(rb + lr) * DDIM + lch * 8;
    const __nv_bfloat16* pb = g_phi + (size_t)(cb + lr) * DDIM + lch * 8;
    const __nv_bfloat16* ab = g_ahi + (size_t)(cb + lr) * DDIM + lch * 8;
    const uint32_t ldoff = lr * ROWB + lch * 16;

    #define ISSUE_X(base, ko)                                                  \
        do {                                                                   \
            const uint32_t _d = (base) + ldoff;                                \
            CP_ASYNC16(_d,              xb + (ko));                            \
            CP_ASYNC16(_d + 32 * ROWB,  xb + (ko) + (size_t)32 * DDIM);        \
            CP_ASYNC16(_d + 64 * ROWB,  xb + (ko) + (size_t)64 * DDIM);        \
            CP_ASYNC16(_d + 96 * ROWB,  xb + (ko) + (size_t)96 * DDIM);        \
        } while (0)
    #define ISSUE_PA(base, ko)                                                 \
        do {                                                                   \
            const uint32_t _d = (base) + ldoff;                                \
            CP_ASYNC16(_d + 128 * ROWB, pb + (ko));                            \
            CP_ASYNC16(_d + 160 * ROWB, pb + (ko) + (size_t)32 * DDIM);        \
            CP_ASYNC16(_d + 192 * ROWB, ab + (ko));                            \
            CP_ASYNC16(_d + 224 * ROWB, ab + (ko) + (size_t)32 * DDIM);        \
        } while (0)

    // ldmatrix lane mappings
    const int a_r = lane & 15;
    const int a_c = lane >> 4;
    const int b_r = (lane & 7) | ((lane & 16) >> 1);
    const int b_h = (lane >> 3) & 1;
    const uint32_t smA = (wm * 64 + a_r) * ROWB + a_c * 16;
    const uint32_t smP = (128 + wn * 16 + b_r) * ROWB + b_h * 16;
    const uint32_t smQ = (192 + wn * 16 + b_r) * ROWB + b_h * 16;
    const uint32_t kof0 = (rot & 3) * 32;

    float cP[4][2][4];
    float cA[4][2][4];
    #pragma unroll
    for (int mt = 0; mt < 4; mt++)
        #pragma unroll
        for (int nt = 0; nt < 2; nt++)
            #pragma unroll
            for (int i = 0; i < 4; i++) { cP[mt][nt][i] = 0.f; cA[mt][nt][i] = 0.f; }

    // pre-arm free[2] (one arrive per warp)
    if (lane == 0) MB_ARRIVE(sb + 24 + 16);

    // prologue: stages 0 and 1; wait stage 0 and preload first B frags
    ISSUE_X(sb + STG0, 0);             ISSUE_PA(sb + STG0, 0);
    CPX_ARRIVE(sb + 0);
    ISSUE_X(sb + STG0 + STAGEB, BK);   ISSUE_PA(sb + STG0 + STAGEB, BK);
    CPX_ARRIVE(sb + 8);

    uint32_t bp[2][4], ba[2][4];
    MBARRIER_WAIT_PARITY(sb + 0, 0);
    LDSM4(bp[0], sb + STG0 + smP + kof0);
    LDSM4(ba[0], sb + STG0 + smQ + kof0);

    // One k-iteration; rolling 2-deep A buffer (xh), mt processed in halves.
    #define KITER(FS, IS, NS, KO2, DO_ISSUE, DO_NEXT, NPAR)                    \
    {                                                                          \
        const uint32_t st  = sb + STG0 + (FS) * STAGEB;                        \
        const uint32_t stn = sb + STG0 + (NS) * STAGEB;                        \
        _Pragma("unroll")                                                      \
        for (int ks = 0; ks < 4; ks++) {                                       \
            const int cur = ks & 1;                                            \
            const uint32_t kofs = ((ks + rot) & 3) * 32;                       \
            uint32_t xh[2][4];                                                 \
            LDSM4(xh[0], st + smA + kofs);                                     \
            LDSM4(xh[1], st + smA + 16 * ROWB + kofs);                         \
            if (ks < 3) {                                                      \
                const uint32_t knx = ((ks + 1 + rot) & 3) * 32;                \
                LDSM4(bp[cur ^ 1], st + smP + knx);                            \
                LDSM4(ba[cur ^ 1], st + smQ + knx);                            \
            }                                                                  \
            if ((DO_ISSUE) && ks == 1) {                                       \
                MBARRIER_WAIT_PARITY_RELAXED(sb + 24 + (IS) * 8, pm);          \
                ISSUE_X(sb + STG0 + (IS) * STAGEB, KO2);                       \
            }                                                                  \
            _Pragma("unroll")                                                  \
            for (int mt = 0; mt < 2; mt++) {                                   \
                _Pragma("unroll")                                              \
                for (int nt = 0; nt < 2; nt++) {                               \
                    MMA16816(cP[mt][nt], xh[mt], bp[cur][nt * 2], bp[cur][nt * 2 + 1]); \
                    MMA16816(cA[mt][nt], xh[mt], ba[cur][nt * 2], ba[cur][nt * 2 + 1]); \
                }                                                              \
            }                                                                  \
            LDSM4(xh[0], st + smA + 32 * ROWB + kofs);                         \
            LDSM4(xh[1], st + smA + 48 * ROWB + kofs);                         \
            if (ks == 3 && lane == 0) MB_ARRIVE(sb + 24 + (FS) * 8);           \
            if ((DO_ISSUE) && ks == 2) {                                       \
                ISSUE_PA(sb + STG0 + (IS) * STAGEB, KO2);                      \
                CPX_ARRIVE(sb + (IS) * 8);                                     \
            }                                                                  \
            if ((DO_NEXT) && ks == 2)                                          \
                MBARRIER_WAIT_PARITY(sb + (NS) * 8, NPAR);                     \
            if ((DO_NEXT) && ks == 3) {                                        \
                LDSM4(bp[0], stn + smP + kof0);                                \
                LDSM4(ba[0], stn + smQ + kof0);                                \
            }                                                                  \
            _Pragma("unroll")                                                  \
            for (int mt = 0; mt < 2; mt++) {                                   \
                _Pragma("unroll")                                              \
                for (int nt = 0; nt < 2; nt++) {                               \
                    MMA16816(cP[mt + 2][nt], xh[mt], bp[cur][nt * 2], bp[cur][nt * 2 + 1]); \
                    MMA16816(cA[mt + 2][nt], xh[mt], ba[cur][nt * 2], ba[cur][nt * 2 + 1]); \
                }                                                              \
            }                                                                  \
        }                                                                      \
    }

    uint32_t pm = 0;
    size_t kb = 0;
    #pragma unroll 1
    for (int m = 0; m < 5; m++) {      // k = 3m .. 3m+2 (k = 0..14)
        KITER(0, 2, 1, kb + 2 * BK, true, true, pm);
        KITER(1, 0, 2, kb + 3 * BK, true, true, pm);
        KITER(2, 1, 0, kb + 4 * BK, true, true, pm ^ 1);
        pm ^= 1;
        kb += 3 * BK;
    }
    KITER(0, 2, 1, 0, false, false, pm);   // k = 15

    // epilogue (registers only); hoisted per-class scalars; streaming stores
    const int g  = lane >> 2;
    const int tg = lane & 3;
    const int colb = cb + wn * 16 + tg * 2;
    float p2c[4], pac[4], anc[4];
    #pragma unroll
    for (int nt = 0; nt < 2; nt++) {
        p2c[nt * 2]     = g_p2[colb + nt * 8];
        p2c[nt * 2 + 1] = g_p2[colb + nt * 8 + 1];
        pac[nt * 2]     = g_pa[colb + nt * 8];
        pac[nt * 2 + 1] = g_pa[colb + nt * 8 + 1];
        anc[nt * 2]     = g_an[colb + nt * 8];
        anc[nt * 2 + 1] = g_an[colb + nt * 8 + 1];
    }
    #pragma unroll
    for (int mt = 0; mt < 4; mt++) {
        #pragma unroll
        for (int h = 0; h < 2; h++) {
            const int row = rb + wm * 64 + mt * 16 + h * 8 + g;
            const float x2 = g_x2[row];
            float* orow = out + (size_t)row * CDIM + cb + wn * 16;
            #pragma unroll
            for (int nt = 0; nt < 2; nt++) {
                float rx = hyp_logit(cP[mt][nt][2 * h],     cA[mt][nt][2 * h],     x2,
                                     p2c[nt * 2],     pac[nt * 2],     anc[nt * 2]);
                float ry = hyp_logit(cP[mt][nt][2 * h + 1], cA[mt][nt][2 * h + 1], x2,
                                     p2c[nt * 2 + 1], pac[nt * 2 + 1], anc[nt * 2 + 1]);
                STG_CS_V2(orow + nt * 8 + tg * 2, rx, ry);
            }
        }
    }
    #undef KITER
    #undef ISSUE_X
    #undef ISSUE_PA
}

// ---------------------------------------------------------------------------
extern "C" void kernel_launch(void* const* d_in, const int* in_sizes, int n_in,
                              void* d_out, int out_size) {
    const float* x = (const float*)d_in[0];
    const float* a = (const float*)d_in[1];
    const float* p = (const float*)d_in[2];
    float* out = (float*)d_out;

    cudaFuncSetAttribute(mlr_mma_kernel,
                         cudaFuncAttributeMaxDynamicSharedMemorySize, SMEM_NEED);

    prep_kernel<<<BDIM + CDIM, 256>>>(x, a, p);
    dim3 grid(CDIM / BN, BDIM / BM);
    mlr_mma_kernel<<<grid, 256, SMEM_NEED>>>(out);
}

// round 16
// speedup vs baseline: 1.0312x; 1.0312x over previous
#include <cuda_runtime.h>
#include <cuda_bf16.h>
#include <math.h>
#include <cstdint>

// Fixed shapes for HyperbolicMLR_33045478375870
#define BDIM 4096
#define DDIM 1024
#define CDIM 4096
#define EPSV 1e-15f
#define MAXN 0.99999f   // (1 - 1e-5)/sqrt(c), c = 1

// ---------------------------------------------------------------------------
// Device scratch (no allocations allowed)
// ---------------------------------------------------------------------------
__device__ __nv_bfloat16 g_xhi[(size_t)BDIM * DDIM];
__device__ __nv_bfloat16 g_phi[(size_t)CDIM * DDIM];
__device__ __nv_bfloat16 g_ahi[(size_t)CDIM * DDIM];
__device__ float g_x2[BDIM];
__device__ float g_p2[CDIM];
__device__ float g_pa[CDIM];
__device__ float g_an[CDIM];

// ---------------------------------------------------------------------------
__device__ __forceinline__ uint32_t smem_u32(const void* p) {
    uint32_t a;
    asm("{ .reg .u64 t; cvta.to.shared.u64 t, %1; cvt.u32.u64 %0, t; }"
        : "=r"(a) : "l"(p));
    return a;
}

#define LDSM4(r, addr) \
    asm volatile("ldmatrix.sync.aligned.m8n8.x4.shared.b16 {%0,%1,%2,%3}, [%4];" \
                 : "=r"((r)[0]), "=r"((r)[1]), "=r"((r)[2]), "=r"((r)[3]) \
                 : "r"(addr))

#define MMA16816(c, a, b0, b1) \
    asm volatile("mma.sync.aligned.m16n8k16.row.col.f32.bf16.bf16.f32 " \
                 "{%0,%1,%2,%3},{%4,%5,%6,%7},{%8,%9},{%0,%1,%2,%3};" \
                 : "+f"((c)[0]), "+f"((c)[1]), "+f"((c)[2]), "+f"((c)[3]) \
                 : "r"((a)[0]), "r"((a)[1]), "r"((a)[2]), "r"((a)[3]), \
                   "r"(b0), "r"(b1))

#define CP_ASYNC16(dst, src) \
    asm volatile("cp.async.cg.shared.global [%0], [%1], 16;" \
                 :: "r"(dst), "l"(__cvta_generic_to_global(src)))

// Streaming store: write-once output should not evict L2-resident operands.
#define STG_CS_V2(addr, vx, vy) \
    asm volatile("st.global.cs.v2.f32 [%0], {%1, %2};" \
                 :: "l"(addr), "f"(vx), "f"(vy) : "memory")

#define MBARRIER_INIT(mbar, count) \
    asm volatile("mbarrier.init.shared.b64 [%0], %1;" \
                 :: "r"((uint32_t)(mbar)), "r"((uint32_t)(count)) : "memory")

#define MB_ARRIVE(mbar) \
    asm volatile("mbarrier.arrive.shared.b64 _, [%0];" \
                 :: "r"((uint32_t)(mbar)) : "memory")

// Branch-free elected arrive: predicated @p arrive, no BSSY/BSYNC envelope.
#define MB_ARRIVE_LANE0(mbar, lane) \
    asm volatile("{\n\t.reg .pred p;\n\t" \
                 "setp.eq.u32 p, %1, 0;\n\t" \
                 "@p mbarrier.arrive.shared.b64 _, [%0];\n\t}" \
                 :: "r"((uint32_t)(mbar)), "r"((uint32_t)(lane)) : "memory")

#define CPX_ARRIVE(mbar) \
    asm volatile("cp.async.mbarrier.arrive.noinc.shared.b64 [%0];" \
                 :: "r"((uint32_t)(mbar)) : "memory")

#define MBARRIER_WAIT_PARITY(mbar, parity) do {                                   \
    uint32_t _mbar = (uint32_t)(mbar);                                            \
    uint32_t _par  = (uint32_t)(parity);                                          \
    uint32_t _done;                                                               \
    asm volatile(                                                                 \
        "{\n\t.reg .pred p;\n\t"                                                  \
        "mbarrier.try_wait.parity.acquire.cta.shared::cta.b64 p, [%1], %2;\n\t"   \
        "selp.b32 %0, 1, 0, p;\n\t}"                                              \
        : "=r"(_done) : "r"(_mbar), "r"(_par) : "memory");                        \
    if (!_done) {                                                                 \
        asm volatile(                                                             \
            "{\n\t.reg .pred P1;\n\t"                                             \
            "WAIT_LOOP_%=:\n\t"                                                   \
            "mbarrier.try_wait.parity.acquire.cta.shared::cta.b64 P1, [%0], %1, 0x989680;\n\t" \
            "@P1 bra.uni WAIT_DONE_%=;\n\t"                                       \
            "bra.uni WAIT_LOOP_%=;\n\t"                                           \
            "WAIT_DONE_%=:\n\t}"                                                  \
            :: "r"(_mbar), "r"(_par) : "memory");                                 \
    }                                                                             \
} while (0)

// Producer wait: post-wait accesses are async-proxy (cp.async) only -> relaxed.
#define MBARRIER_WAIT_PARITY_RELAXED(mbar, parity) do {                           \
    uint32_t _mbar = (uint32_t)(mbar);                                            \
    uint32_t _par  = (uint32_t)(parity);                                          \
    uint32_t _done;                                                               \
    asm volatile(                                                                 \
        "{\n\t.reg .pred p;\n\t"                                                  \
        "mbarrier.try_wait.parity.relaxed.cta.shared::cta.b64 p, [%1], %2;\n\t"   \
        "selp.b32 %0, 1, 0, p;\n\t}"                                              \
        : "=r"(_done) : "r"(_mbar), "r"(_par) : "memory");                        \
    if (!_done) {                                                                 \
        asm volatile(                                                             \
            "{\n\t.reg .pred P1;\n\t"                                             \
            "WAIT_LOOP_%=:\n\t"                                                   \
            "mbarrier.try_wait.parity.relaxed.cta.shared::cta.b64 P1, [%0], %1, 0x989680;\n\t" \
            "@P1 bra.uni WAIT_DONE_%=;\n\t"                                       \
            "bra.uni WAIT_LOOP_%=;\n\t"                                           \
            "WAIT_DONE_%=:\n\t}"                                                  \
            :: "r"(_mbar), "r"(_par) : "memory");                                 \
    }                                                                             \
} while (0)

// ---------------------------------------------------------------------------
// Merged prep kernel (unchanged)
// ---------------------------------------------------------------------------
__global__ __launch_bounds__(256) void prep_kernel(const float* __restrict__ x,
                                                   const float* __restrict__ a,
                                                   const float* __restrict__ p) {
    const int blk = blockIdx.x;
    const int tid = threadIdx.x;
    __shared__ float red[3][8];

    if (blk < BDIM) {
        const int b = blk;
        const float4 v = ((const float4*)(x + (size_t)b * DDIM))[tid];
        float s = v.x * v.x + v.y * v.y + v.z * v.z + v.w * v.w;
        #pragma unroll
        for (int o = 16; o > 0; o >>= 1) s += __shfl_xor_sync(0xFFFFFFFFu, s, o);
        if ((tid & 31) == 0) red[0][tid >> 5] = s;
        __syncthreads();
        __shared__ float sh_scale;
        if (tid == 0) {
            float tot = 0.f;
            #pragma unroll
            for (int w = 0; w < 8; w++) tot += red[0][w];
            float xn = fmaxf(sqrtf(tot), EPSV);
            float scale = (xn > MAXN) ? (MAXN / xn) : 1.0f;
            sh_scale = scale;
            g_x2[b] = tot * scale * scale;
        }
        __syncthreads();
        const float sc = sh_scale;
        __nv_bfloat162 o0 = {__float2bfloat16(v.x * sc), __float2bfloat16(v.y * sc)};
        __nv_bfloat162 o1 = {__float2bfloat16(v.z * sc), __float2bfloat16(v.w * sc)};
        ((__nv_bfloat162*)(g_xhi + (size_t)b * DDIM))[tid * 2]     = o0;
        ((__nv_bfloat162*)(g_xhi + (size_t)b * DDIM))[tid * 2 + 1] = o1;
    } else {
        const int c = blk - BDIM;
        const float4 pv = ((const float4*)(p + (size_t)c * DDIM))[tid];
        const float4 av = ((const float4*)(a + (size_t)c * DDIM))[tid];
        float sp2 = pv.x * pv.x + pv.y * pv.y + pv.z * pv.z + pv.w * pv.w;
        float spa = pv.x * av.x + pv.y * av.y + pv.z * av.z + pv.w * av.w;
        float sa2 = av.x * av.x + av.y * av.y + av.z * av.z + av.w * av.w;
        __nv_bfloat162 p0 = {__float2bfloat16(pv.x), __float2bfloat16(pv.y)};
        __nv_bfloat162 p1 = {__float2bfloat16(pv.z), __float2bfloat16(pv.w)};
        __nv_bfloat162 a0 = {__float2bfloat16(av.x), __float2bfloat16(av.y)};
        __nv_bfloat162 a1 = {__float2bfloat16(av.z), __float2bfloat16(av.w)};
        ((__nv_bfloat162*)(g_phi + (size_t)c * DDIM))[tid * 2]     = p0;
        ((__nv_bfloat162*)(g_phi + (size_t)c * DDIM))[tid * 2 + 1] = p1;
        ((__nv_bfloat162*)(g_ahi + (size_t)c * DDIM))[tid * 2]     = a0;
        ((__nv_bfloat162*)(g_ahi + (size_t)c * DDIM))[tid * 2 + 1] = a1;
        #pragma unroll
        for (int o = 16; o > 0; o >>= 1) {
            sp2 += __shfl_xor_sync(0xFFFFFFFFu, sp2, o);
            spa += __shfl_xor_sync(0xFFFFFFFFu, spa, o);
            sa2 += __shfl_xor_sync(0xFFFFFFFFu, sa2, o);
        }
        if ((tid & 31) == 0) {
            red[0][tid >> 5] = sp2; red[1][tid >> 5] = spa; red[2][tid >> 5] = sa2;
        }
        __syncthreads();
        if (tid == 0) {
            float t0 = 0.f, t1 = 0.f, t2 = 0.f;
            #pragma unroll
            for (int w = 0; w < 8; w++) { t0 += red[0][w]; t1 += red[1][w]; t2 += red[2][w]; }
            g_p2[c] = t0; g_pa[c] = t1; g_an[c] = sqrtf(t2);
        }
    }
}

// ---------------------------------------------------------------------------
// Epilogue math: 1 MUFU (rsqrt), no division, no log. 10-term atanh poly.
// ---------------------------------------------------------------------------
__device__ __forceinline__ float hyp_logit(float px, float xa, float x2,
                                           float p2, float pa, float an) {
    const float A   = 1.0f - 2.0f * px + x2;
    const float Bc  = 1.0f - p2;
    const float den = fmaxf(fmaf(x2, p2, fmaf(-2.0f, px, 1.0f)), EPSV);
    const float w   = fmaxf(fmaf(A * A, p2, fmaf(Bc * Bc, x2, -2.0f * A * Bc * px)), 0.0f);
    const float u   = fmaf(Bc, xa, -A * pa);
    const float N   = 2.0f * u * den;
    const float D   = fmaf(den, den, w) * an;
    const float z   = N * rsqrtf(fmaf(N, N, D * D));
    const float t   = z * z;
    float s = 1.0f / 19.0f;
    s = fmaf(s, t, 1.0f / 17.0f);
    s = fmaf(s, t, 1.0f / 15.0f); s = fmaf(s, t, 1.0f / 13.0f);
    s = fmaf(s, t, 1.0f / 11.0f); s = fmaf(s, t, 1.0f / 9.0f);
    s = fmaf(s, t, 1.0f / 7.0f);  s = fmaf(s, t, 1.0f / 5.0f);
    s = fmaf(s, t, 1.0f / 3.0f);  s = fmaf(s, t, 1.0f);
    return -z * s;
}

// ---------------------------------------------------------------------------
// Main kernel: dual pure-bf16 GEMM via mma.sync + fused epilogue
//   R14 structure (197.0us best). Change vs R15: the elected free-barrier
//   arrive is PREDICATED (no branch, no BSSY) instead of an if-guard.
//   free[] barriers count 8 (one arrive per warp).
// ---------------------------------------------------------------------------
#define BM 128
#define BN 64
#define BK 64
#define NKIT (DDIM / BK)          // 16
#define ROWB 144                  // 128 data + 16 pad (conflict-free ldmatrix)
#define STAGEB (256 * ROWB)       // 36864
#define STG0 128
#define SMEM_NEED (STG0 + 3 * STAGEB)  // 110720

__global__ __launch_bounds__(256, 2) void mlr_mma_kernel(float* __restrict__ out) {
    extern __shared__ char sm[];
    const uint32_t sb = smem_u32(sm);
    const int tid  = threadIdx.x;
    const int wid  = tid >> 5;
    const int lane = tid & 31;
    const int wn = wid & 3;
    const int wm = wid >> 2;
    const int cb = blockIdx.x * BN;
    const int rb = blockIdx.y * BM;
    const int rot = (wn + (wm << 1)) & 3;   // 4-phase SM-wide spread

    // barriers: full[s] at sb + s*8 (count 256, cp.async tracked);
    //           free[s] at sb + 24 + s*8 (count 8: one arrive per warp)
    if (tid == 0) {
        #pragma unroll
        for (int s = 0; s < 3; s++) {
            MBARRIER_INIT(sb + s * 8, 256);
            MBARRIER_INIT(sb + 24 + s * 8, 8);
        }
    }
    __syncthreads();

    // loader mapping
    const int lr = tid >> 3;
    const int lch = tid & 7;
    const __nv_bfloat16* xb = g_xhi + (size_t)(rb + lr) * DDIM + lch * 8;
    const __nv_bfloat16* pb = g_phi + (size_t)(cb + lr) * DDIM + lch * 8;
    const __nv_bfloat16* ab = g_ahi + (size_t)(cb + lr) * DDIM + lch * 8;
    const uint32_t ldoff = lr * ROWB + lch * 16;

    #define ISSUE_X(base, ko)                                                  \
        do {                                                                   \
            const uint32_t _d = (base) + ldoff;                                \
            CP_ASYNC16(_d,              xb + (ko));                            \
            CP_ASYNC16(_d + 32 * ROWB,  xb + (ko) + (size_t)32 * DDIM);        \
            CP_ASYNC16(_d + 64 * ROWB,  xb + (ko) + (size_t)64 * DDIM);        \
            CP_ASYNC16(_d + 96 * ROWB,  xb + (ko) + (size_t)96 * DDIM);        \
        } while (0)
    #define ISSUE_PA(base, ko)                                                 \
        do {                                                                   \
            const uint32_t _d = (base) + ldoff;                                \
            CP_ASYNC16(_d + 128 * ROWB, pb + (ko));                            \
            CP_ASYNC16(_d + 160 * ROWB, pb + (ko) + (size_t)32 * DDIM);        \
            CP_ASYNC16(_d + 192 * ROWB, ab + (ko));                            \
            CP_ASYNC16(_d + 224 * ROWB, ab + (ko) + (size_t)32 * DDIM);        \
        } while (0)

    // ldmatrix lane mappings
    const int a_r = lane & 15;
    const int a_c = lane >> 4;
    const int b_r = (lane & 7) | ((lane & 16) >> 1);
    const int b_h = (lane >> 3) & 1;
    const uint32_t smA = (wm * 64 + a_r) * ROWB + a_c * 16;
    const uint32_t smP = (128 + wn * 16 + b_r) * ROWB + b_h * 16;
    const uint32_t smQ = (192 + wn * 16 + b_r) * ROWB + b_h * 16;
    const uint32_t kof0 = (rot & 3) * 32;

    float cP[4][2][4];
    float cA[4][2][4];
    #pragma unroll
    for (int mt = 0; mt < 4; mt++)
        #pragma unroll
        for (int nt = 0; nt < 2; nt++)
            #pragma unroll
            for (int i = 0; i < 4; i++) { cP[mt][nt][i] = 0.f; cA[mt][nt][i] = 0.f; }

    // pre-arm free[2] (predicated elected arrive per warp)
    MB_ARRIVE_LANE0(sb + 24 + 16, lane);

    // prologue: stages 0 and 1; wait stage 0 and preload first B frags
    ISSUE_X(sb + STG0, 0);             ISSUE_PA(sb + STG0, 0);
    CPX_ARRIVE(sb + 0);
    ISSUE_X(sb + STG0 + STAGEB, BK);   ISSUE_PA(sb + STG0 + STAGEB, BK);
    CPX_ARRIVE(sb + 8);

    uint32_t bp[2][4], ba[2][4];
    MBARRIER_WAIT_PARITY(sb + 0, 0);
    LDSM4(bp[0], sb + STG0 + smP + kof0);
    LDSM4(ba[0], sb + STG0 + smQ + kof0);

    // One k-iteration; rolling 2-deep A buffer (xh), mt processed in halves.
    #define KITER(FS, IS, NS, KO2, DO_ISSUE, DO_NEXT, NPAR)                    \
    {                                                                          \
        const uint32_t st  = sb + STG0 + (FS) * STAGEB;                        \
        const uint32_t stn = sb + STG0 + (NS) * STAGEB;                        \
        _Pragma("unroll")                                                      \
        for (int ks = 0; ks < 4; ks++) {                                       \
            const int cur = ks & 1;                                            \
            const uint32_t kofs = ((ks + rot) & 3) * 32;                       \
            uint32_t xh[2][4];                                                 \
            LDSM4(xh[0], st + smA + kofs);                                     \
            LDSM4(xh[1], st + smA + 16 * ROWB + kofs);                         \
            if (ks < 3) {                                                      \
                const uint32_t knx = ((ks + 1 + rot) & 3) * 32;                \
                LDSM4(bp[cur ^ 1], st + smP + knx);                            \
                LDSM4(ba[cur ^ 1], st + smQ + knx);                            \
            }                                                                  \
            if ((DO_ISSUE) && ks == 1) {                                       \
                MBARRIER_WAIT_PARITY_RELAXED(sb + 24 + (IS) * 8, pm);          \
                ISSUE_X(sb + STG0 + (IS) * STAGEB, KO2);                       \
            }                                                                  \
            _Pragma("unroll")                                                  \
            for (int mt = 0; mt < 2; mt++) {                                   \
                _Pragma("unroll")                                              \
                for (int nt = 0; nt < 2; nt++) {                               \
                    MMA16816(cP[mt][nt], xh[mt], bp[cur][nt * 2], bp[cur][nt * 2 + 1]); \
                    MMA16816(cA[mt][nt], xh[mt], ba[cur][nt * 2], ba[cur][nt * 2 + 1]); \
                }                                                              \
            }                                                                  \
            LDSM4(xh[0], st + smA + 32 * ROWB + kofs);                         \
            LDSM4(xh[1], st + smA + 48 * ROWB + kofs);                         \
            if (ks == 3) MB_ARRIVE_LANE0(sb + 24 + (FS) * 8, lane);            \
            if ((DO_ISSUE) && ks == 2) {                                       \
                ISSUE_PA(sb + STG0 + (IS) * STAGEB, KO2);                      \
                CPX_ARRIVE(sb + (IS) * 8);                                     \
            }                                                                  \
            if ((DO_NEXT) && ks == 2)                                          \
                MBARRIER_WAIT_PARITY(sb + (NS) * 8, NPAR);                     \
            if ((DO_NEXT) && ks == 3) {                                        \
                LDSM4(bp[0], stn + smP + kof0);                                \
                LDSM4(ba[0], stn + smQ + kof0);                                \
            }                                                                  \
            _Pragma("unroll")                                                  \
            for (int mt = 0; mt < 2; mt++) {                                   \
                _Pragma("unroll")                                              \
                for (int nt = 0; nt < 2; nt++) {                               \
                    MMA16816(cP[mt + 2][nt], xh[mt], bp[cur][nt * 2], bp[cur][nt * 2 + 1]); \
                    MMA16816(cA[mt + 2][nt], xh[mt], ba[cur][nt * 2], ba[cur][nt * 2 + 1]); \
                }                                                              \
            }                                                                  \
        }                                                                      \
    }

    uint32_t pm = 0;
    size_t kb = 0;
    #pragma unroll 1
    for (int m = 0; m < 5; m++) {      // k = 3m .. 3m+2 (k = 0..14)
        KITER(0, 2, 1, kb + 2 * BK, true, true, pm);
        KITER(1, 0, 2, kb + 3 * BK, true, true, pm);
        KITER(2, 1, 0, kb + 4 * BK, true, true, pm ^ 1);
        pm ^= 1;
        kb += 3 * BK;
    }
    KITER(0, 2, 1, 0, false, false, pm);   // k = 15

    // epilogue (registers only); hoisted per-class scalars; streaming stores
    const int g  = lane >> 2;
    const int tg = lane & 3;
    const int colb = cb + wn * 16 + tg * 2;
    float p2c[4], pac[4], anc[4];
    #pragma unroll
    for (int nt = 0; nt < 2; nt++) {
        p2c[nt * 2]     = g_p2[colb + nt * 8];
        p2c[nt * 2 + 1] = g_p2[colb + nt * 8 + 1];
        pac[nt * 2]     = g_pa[colb + nt * 8];
        pac[nt * 2 + 1] = g_pa[colb + nt * 8 + 1];
        anc[nt * 2]     = g_an[colb + nt * 8];
        anc[nt * 2 + 1] = g_an[colb + nt * 8 + 1];
    }
    #pragma unroll
    for (int mt = 0; mt < 4; mt++) {
        #pragma unroll
        for (int h = 0; h < 2; h++) {
            const int row = rb + wm * 64 + mt * 16 + h * 8 + g;
            const float x2 = g_x2[row];
            float* orow = out + (size_t)row * CDIM + cb + wn * 16;
            #pragma unroll
            for (int nt = 0; nt < 2; nt++) {
                float rx = hyp_logit(cP[mt][nt][2 * h],     cA[mt][nt][2 * h],     x2,
                                     p2c[nt * 2],     pac[nt * 2],     anc[nt * 2]);
                float ry = hyp_logit(cP[mt][nt][2 * h + 1], cA[mt][nt][2 * h + 1], x2,
                                     p2c[nt * 2 + 1], pac[nt * 2 + 1], anc[nt * 2 + 1]);
                STG_CS_V2(orow + nt * 8 + tg * 2, rx, ry);
            }
        }
    }
    #undef KITER
    #undef ISSUE_X
    #undef ISSUE_PA
}

// ---------------------------------------------------------------------------
extern "C" void kernel_launch(void* const* d_in, const int* in_sizes, int n_in,
                              void* d_out, int out_size) {
    const float* x = (const float*)d_in[0];
    const float* a = (const float*)d_in[1];
    const float* p = (const float*)d_in[2];
    float* out = (float*)d_out;

    cudaFuncSetAttribute(mlr_mma_kernel,
                         cudaFuncAttributeMaxDynamicSharedMemorySize, SMEM_NEED);

    prep_kernel<<<BDIM + CDIM, 256>>>(x, a, p);
    dim3 grid(CDIM / BN, BDIM / BM);
    mlr_mma_kernel<<<grid, 256, SMEM_NEED>>>(out);
}